// round 4
// baseline (speedup 1.0000x reference)
#include <cuda_runtime.h>
#include <math_constants.h>

// Problem shape (fixed by the dataset)
#define BB 4
#define HH 32
#define DD 128
#define SS 8192
#define NSPL 37           // splits per batch -> grid = 4*37 = 148 = one CTA per SM
#define NW 8              // warps per CTA; warp w owns heads 4w..4w+3
#define NBH (BB * HH)     // 128
#define SCALE 0.08838834764831845f   // 1/sqrt(128)

// Scratch for split-KV partials (device globals: allocation-free)
// Indexed per (b, split, head).
__device__ float g_pm[BB * NSPL * HH];
__device__ float g_pl[BB * NSPL * HH];
__device__ float g_pacc[(size_t)BB * NSPL * HH * DD];
__device__ int   g_cnt[BB];   // zero-init; self-resetting -> graph-replay safe

__device__ __forceinline__ float warp_sum(float v) {
#pragma unroll
    for (int o = 16; o > 0; o >>= 1)
        v += __shfl_xor_sync(0xffffffffu, v, o);
    return v;
}

__device__ __forceinline__ float dot4(const float4 a, const float4 b) {
    return a.x * b.x + a.y * b.y + a.z * b.z + a.w * b.w;
}

__device__ __forceinline__ float4 ldcs4(const float* p) {
    return __ldcs(reinterpret_cast<const float4*>(p));
}

// ---------------------------------------------------------------------------
// CTA = (b, split): processes positions [s0, s1) for ALL 32 heads.
// Warp w owns heads 4w..4w+3; lane owns dims [4*lane, 4*lane+4).
// Per position each warp reads a CONTIGUOUS 2KB K block and 2KB V block;
// the 8 warps sweep the full 16KB row -> streaming-friendly DRAM pattern.
// ---------------------------------------------------------------------------
__global__ __launch_bounds__(NW * 32, 1)
void attn_seq_kernel(const float* __restrict__ x,
                     const float* __restrict__ kv,
                     const int*   __restrict__ cur_pos,
                     float*       __restrict__ out) {
    const int bid   = blockIdx.x;
    const int b     = bid / NSPL;
    const int split = bid % NSPL;

    const int tid  = threadIdx.x;
    const int lane = tid & 31;
    const int w    = tid >> 5;
    const int h0   = w * 4;

    const int len   = *cur_pos + 1;
    const int chunk = (len + NSPL - 1) / NSPL;
    const int s0    = split * chunk;
    const int s1    = min(len, s0 + chunk);

    // q for this warp's 4 heads (lane's 4 dims each)
    const float* qb = x + (size_t)(b * HH + h0) * DD + lane * 4;
    const float4 q0 = *reinterpret_cast<const float4*>(qb);
    const float4 q1 = *reinterpret_cast<const float4*>(qb + DD);
    const float4 q2 = *reinterpret_cast<const float4*>(qb + 2 * DD);
    const float4 q3 = *reinterpret_cast<const float4*>(qb + 3 * DD);

    const size_t rowHD   = (size_t)HH * DD;              // 4096 floats / position
    const size_t kv_half = (size_t)BB * SS * rowHD;      // K -> V offset
    // base pointer to this warp's 2KB block within a position row
    const float* Kb = kv + (size_t)b * SS * rowHD + (size_t)h0 * DD + lane * 4;
    const float* Vb = Kb + kv_half;

    float m0 = -CUDART_INF_F, m1 = -CUDART_INF_F, m2 = -CUDART_INF_F, m3 = -CUDART_INF_F;
    float l0 = 0.f, l1 = 0.f, l2 = 0.f, l3 = 0.f;
    float4 a0 = make_float4(0, 0, 0, 0), a1 = a0, a2 = a0, a3 = a0;

    int s = s0;
    // 2-position unroll: 16 float4 streaming loads in flight before math.
    for (; s + 1 < s1; s += 2) {
        const float* kA = Kb + (size_t)s * rowHD;
        const float* vA = Vb + (size_t)s * rowHD;
        const float* kB = kA + rowHD;
        const float* vB = vA + rowHD;

        const float4 kA0 = ldcs4(kA);           const float4 kA1 = ldcs4(kA + DD);
        const float4 kA2 = ldcs4(kA + 2 * DD);  const float4 kA3 = ldcs4(kA + 3 * DD);
        const float4 kB0 = ldcs4(kB);           const float4 kB1 = ldcs4(kB + DD);
        const float4 kB2 = ldcs4(kB + 2 * DD);  const float4 kB3 = ldcs4(kB + 3 * DD);
        const float4 vA0 = ldcs4(vA);           const float4 vA1 = ldcs4(vA + DD);
        const float4 vA2 = ldcs4(vA + 2 * DD);  const float4 vA3 = ldcs4(vA + 3 * DD);
        const float4 vB0 = ldcs4(vB);           const float4 vB1 = ldcs4(vB + DD);
        const float4 vB2 = ldcs4(vB + 2 * DD);  const float4 vB3 = ldcs4(vB + 3 * DD);

        const float sA0 = warp_sum(dot4(kA0, q0)) * SCALE;
        const float sB0 = warp_sum(dot4(kB0, q0)) * SCALE;
        const float sA1 = warp_sum(dot4(kA1, q1)) * SCALE;
        const float sB1 = warp_sum(dot4(kB1, q1)) * SCALE;
        const float sA2 = warp_sum(dot4(kA2, q2)) * SCALE;
        const float sB2 = warp_sum(dot4(kB2, q2)) * SCALE;
        const float sA3 = warp_sum(dot4(kA3, q3)) * SCALE;
        const float sB3 = warp_sum(dot4(kB3, q3)) * SCALE;

        // head 0
        {
            const float mn = fmaxf(m0, fmaxf(sA0, sB0));
            const float c  = __expf(m0 - mn);
            const float pA = __expf(sA0 - mn);
            const float pB = __expf(sB0 - mn);
            m0 = mn; l0 = l0 * c + pA + pB;
            a0.x = a0.x * c + pA * vA0.x + pB * vB0.x;
            a0.y = a0.y * c + pA * vA0.y + pB * vB0.y;
            a0.z = a0.z * c + pA * vA0.z + pB * vB0.z;
            a0.w = a0.w * c + pA * vA0.w + pB * vB0.w;
        }
        // head 1
        {
            const float mn = fmaxf(m1, fmaxf(sA1, sB1));
            const float c  = __expf(m1 - mn);
            const float pA = __expf(sA1 - mn);
            const float pB = __expf(sB1 - mn);
            m1 = mn; l1 = l1 * c + pA + pB;
            a1.x = a1.x * c + pA * vA1.x + pB * vB1.x;
            a1.y = a1.y * c + pA * vA1.y + pB * vB1.y;
            a1.z = a1.z * c + pA * vA1.z + pB * vB1.z;
            a1.w = a1.w * c + pA * vA1.w + pB * vB1.w;
        }
        // head 2
        {
            const float mn = fmaxf(m2, fmaxf(sA2, sB2));
            const float c  = __expf(m2 - mn);
            const float pA = __expf(sA2 - mn);
            const float pB = __expf(sB2 - mn);
            m2 = mn; l2 = l2 * c + pA + pB;
            a2.x = a2.x * c + pA * vA2.x + pB * vB2.x;
            a2.y = a2.y * c + pA * vA2.y + pB * vB2.y;
            a2.z = a2.z * c + pA * vA2.z + pB * vB2.z;
            a2.w = a2.w * c + pA * vA2.w + pB * vB2.w;
        }
        // head 3
        {
            const float mn = fmaxf(m3, fmaxf(sA3, sB3));
            const float c  = __expf(m3 - mn);
            const float pA = __expf(sA3 - mn);
            const float pB = __expf(sB3 - mn);
            m3 = mn; l3 = l3 * c + pA + pB;
            a3.x = a3.x * c + pA * vA3.x + pB * vB3.x;
            a3.y = a3.y * c + pA * vA3.y + pB * vB3.y;
            a3.z = a3.z * c + pA * vA3.z + pB * vB3.z;
            a3.w = a3.w * c + pA * vA3.w + pB * vB3.w;
        }
    }
    // tail (at most 1 position)
    for (; s < s1; s++) {
        const float* kA = Kb + (size_t)s * rowHD;
        const float* vA = Vb + (size_t)s * rowHD;
        const float4 k0 = ldcs4(kA);          const float4 k1 = ldcs4(kA + DD);
        const float4 k2 = ldcs4(kA + 2 * DD); const float4 k3 = ldcs4(kA + 3 * DD);
        const float4 v0 = ldcs4(vA);          const float4 v1 = ldcs4(vA + DD);
        const float4 v2 = ldcs4(vA + 2 * DD); const float4 v3 = ldcs4(vA + 3 * DD);

        const float sc0 = warp_sum(dot4(k0, q0)) * SCALE;
        const float sc1 = warp_sum(dot4(k1, q1)) * SCALE;
        const float sc2 = warp_sum(dot4(k2, q2)) * SCALE;
        const float sc3 = warp_sum(dot4(k3, q3)) * SCALE;

        { const float mn = fmaxf(m0, sc0); const float c = __expf(m0 - mn); const float p = __expf(sc0 - mn);
          m0 = mn; l0 = l0 * c + p;
          a0.x = a0.x * c + p * v0.x; a0.y = a0.y * c + p * v0.y; a0.z = a0.z * c + p * v0.z; a0.w = a0.w * c + p * v0.w; }
        { const float mn = fmaxf(m1, sc1); const float c = __expf(m1 - mn); const float p = __expf(sc1 - mn);
          m1 = mn; l1 = l1 * c + p;
          a1.x = a1.x * c + p * v1.x; a1.y = a1.y * c + p * v1.y; a1.z = a1.z * c + p * v1.z; a1.w = a1.w * c + p * v1.w; }
        { const float mn = fmaxf(m2, sc2); const float c = __expf(m2 - mn); const float p = __expf(sc2 - mn);
          m2 = mn; l2 = l2 * c + p;
          a2.x = a2.x * c + p * v2.x; a2.y = a2.y * c + p * v2.y; a2.z = a2.z * c + p * v2.z; a2.w = a2.w * c + p * v2.w; }
        { const float mn = fmaxf(m3, sc3); const float c = __expf(m3 - mn); const float p = __expf(sc3 - mn);
          m3 = mn; l3 = l3 * c + p;
          a3.x = a3.x * c + p * v3.x; a3.y = a3.y * c + p * v3.y; a3.z = a3.z * c + p * v3.z; a3.w = a3.w * c + p * v3.w; }
    }

    // ---- write per-head partials (warps own disjoint heads: no CTA reduce) ----
    {
        const int base = (b * NSPL + split) * HH + h0;
        if (lane == 0) {
            g_pm[base + 0] = m0; g_pl[base + 0] = l0;
            g_pm[base + 1] = m1; g_pl[base + 1] = l1;
            g_pm[base + 2] = m2; g_pl[base + 2] = l2;
            g_pm[base + 3] = m3; g_pl[base + 3] = l3;
        }
        float4* pa = reinterpret_cast<float4*>(g_pacc + (size_t)base * DD) + lane;
        pa[0]          = a0;
        pa[DD / 4]     = a1;
        pa[2 * DD / 4] = a2;
        pa[3 * DD / 4] = a3;
    }

    // ---- fused cross-split combine: last CTA per batch merges all splits ----
    __threadfence();
    __shared__ int s_last;
    if (tid == 0) s_last = (atomicAdd(&g_cnt[b], 1) == NSPL - 1) ? 1 : 0;
    __syncthreads();

    if (s_last) {
#pragma unroll
        for (int j = 0; j < 4; j++) {
            const int h = h0 + j;
            float M = -CUDART_INF_F;
#pragma unroll 4
            for (int i = 0; i < NSPL; i++)
                M = fmaxf(M, __ldcg(&g_pm[(b * NSPL + i) * HH + h]));

            float  L = 0.f;
            float4 o = make_float4(0, 0, 0, 0);
#pragma unroll 4
            for (int i = 0; i < NSPL; i++) {
                const int idx = (b * NSPL + i) * HH + h;
                const float li = __ldcg(&g_pl[idx]);
                if (li == 0.f) continue;
                const float c = __expf(__ldcg(&g_pm[idx]) - M);
                L += c * li;
                const float4 a = __ldcg(reinterpret_cast<const float4*>(
                    g_pacc + (size_t)idx * DD) + lane);
                o.x += c * a.x; o.y += c * a.y; o.z += c * a.z; o.w += c * a.w;
            }
            const float inv = 1.f / L;
            const float4 r = make_float4(o.x * inv, o.y * inv, o.z * inv, o.w * inv);
            reinterpret_cast<float4*>(out + (size_t)(b * HH + h) * DD)[lane] = r;
        }
        if (tid == 0) g_cnt[b] = 0;   // reset for next graph replay
    }
}

// ---------------------------------------------------------------------------
extern "C" void kernel_launch(void* const* d_in, const int* in_sizes, int n_in,
                              void* d_out, int out_size) {
    // Identify inputs defensively by element count:
    //   x: B*H*D = 16384 fp32, kv: 2*B*S*H*D fp32 (largest), current_pos: 1 int
    const float* x  = nullptr;
    const float* kv = nullptr;
    const int*   cp = nullptr;
    long long best_kv = -1;
    for (int i = 0; i < n_in; i++) {
        if (in_sizes[i] == 1) cp = (const int*)d_in[i];
        else if (in_sizes[i] == BB * HH * DD) x = (const float*)d_in[i];
        else if ((long long)in_sizes[i] > best_kv) {
            best_kv = in_sizes[i];
            kv = (const float*)d_in[i];
        }
    }

    attn_seq_kernel<<<BB * NSPL, NW * 32>>>(x, kv, cp, (float*)d_out);
}

// round 5
// speedup vs baseline: 1.5760x; 1.5760x over previous
#include <cuda_runtime.h>
#include <math_constants.h>

// Problem shape (fixed by the dataset)
#define BB 4
#define HH 32
#define DD 128
#define SS 8192
#define NSPLITS 8
#define NWARPS 4          // warps per split CTA
#define NBH (BB * HH)     // 128
#define SCALE 0.08838834764831845f   // 1/sqrt(128)

// Scratch for split-KV partials (device globals: allocation-free)
__device__ float g_pm[NBH * NSPLITS];
__device__ float g_pl[NBH * NSPLITS];
__device__ float g_pacc[NBH * NSPLITS * DD];
__device__ int   g_cnt[NBH];   // zero-init; self-resetting -> graph-replay safe

__device__ __forceinline__ float warp_sum(float v) {
#pragma unroll
    for (int o = 16; o > 0; o >>= 1)
        v += __shfl_xor_sync(0xffffffffu, v, o);
    return v;
}

__device__ __forceinline__ float dot4(const float4 a, const float4 b) {
    return a.x * b.x + a.y * b.y + a.z * b.z + a.w * b.w;
}

// ---------------------------------------------------------------------------
// One CTA = one (b, h, split). Warps stride positions inside the split chunk.
// Lane owns dims [4*lane, 4*lane+4). Combine is fused: the last CTA per (b,h)
// merges all split partials and writes the final output.
// Mainloop: 2x position unroll -> 4 float4 loads in flight per warp
// (MLP_p1 = 4; R2/R3 showed deeper front-batching regresses at this occupancy).
// ---------------------------------------------------------------------------
__global__ __launch_bounds__(NWARPS * 32)
void attn_split_kernel(const float* __restrict__ x,
                       const float* __restrict__ kv,
                       const int*   __restrict__ cur_pos,
                       float*       __restrict__ out) {
    const int bid   = blockIdx.x;            // b*H*NSPLITS + h*NSPLITS + split
    const int bh    = bid / NSPLITS;
    const int h     = bh % HH;
    const int b     = bh / HH;
    const int split = bid % NSPLITS;

    const int tid  = threadIdx.x;
    const int lane = tid & 31;
    const int w    = tid >> 5;

    const int len   = *cur_pos + 1;                      // valid positions
    const int chunk = (len + NSPLITS - 1) / NSPLITS;
    const int s0    = split * chunk;
    const int s1    = min(len, s0 + chunk);

    // q[b,0,h,:] — lane's 4 dims
    const float4 q = *reinterpret_cast<const float4*>(
        x + (size_t)(b * HH + h) * DD + lane * 4);

    const size_t row_stride = (size_t)HH * DD;           // stride over s
    const size_t kv_half    = (size_t)BB * SS * HH * DD; // K->V offset
    const float* Kp = kv + (size_t)b * SS * row_stride + (size_t)h * DD + lane * 4;
    const float* Vp = Kp + kv_half;

    float  m = -CUDART_INF_F;
    float  l = 0.f;
    float4 acc = make_float4(0.f, 0.f, 0.f, 0.f);

    int s = s0 + w;
    // 2x unroll: 4 float4 loads in flight, single max/rescale per pair.
    for (; s + NWARPS < s1; s += 2 * NWARPS) {
        const float4 kA = *reinterpret_cast<const float4*>(Kp + (size_t)(s         ) * row_stride);
        const float4 vA = *reinterpret_cast<const float4*>(Vp + (size_t)(s         ) * row_stride);
        const float4 kB = *reinterpret_cast<const float4*>(Kp + (size_t)(s + NWARPS) * row_stride);
        const float4 vB = *reinterpret_cast<const float4*>(Vp + (size_t)(s + NWARPS) * row_stride);

        const float scA = warp_sum(dot4(kA, q)) * SCALE;
        const float scB = warp_sum(dot4(kB, q)) * SCALE;

        const float mn   = fmaxf(m, fmaxf(scA, scB));
        const float corr = __expf(m - mn);
        const float pA   = __expf(scA - mn);
        const float pB   = __expf(scB - mn);
        m = mn;
        l = l * corr + (pA + pB);
        acc.x = acc.x * corr + pA * vA.x + pB * vB.x;
        acc.y = acc.y * corr + pA * vA.y + pB * vB.y;
        acc.z = acc.z * corr + pA * vA.z + pB * vB.z;
        acc.w = acc.w * corr + pA * vA.w + pB * vB.w;
    }
    for (; s < s1; s += NWARPS) {
        const float4 kk = *reinterpret_cast<const float4*>(Kp + (size_t)s * row_stride);
        const float4 vv = *reinterpret_cast<const float4*>(Vp + (size_t)s * row_stride);
        const float sc = warp_sum(dot4(kk, q)) * SCALE;
        const float mn   = fmaxf(m, sc);
        const float corr = __expf(m - mn);
        const float p    = __expf(sc - mn);
        m = mn;
        l = l * corr + p;
        acc.x = acc.x * corr + p * vv.x;
        acc.y = acc.y * corr + p * vv.y;
        acc.z = acc.z * corr + p * vv.z;
        acc.w = acc.w * corr + p * vv.w;
    }

    // ---- combine the NWARPS warps of this CTA ----
    __shared__ float sm_m[NWARPS];
    __shared__ float sm_l[NWARPS];
    __shared__ float sm_acc[NWARPS][DD];

    if (lane == 0) { sm_m[w] = m; sm_l[w] = l; }
    sm_acc[w][lane * 4 + 0] = acc.x;
    sm_acc[w][lane * 4 + 1] = acc.y;
    sm_acc[w][lane * 4 + 2] = acc.z;
    sm_acc[w][lane * 4 + 3] = acc.w;
    __syncthreads();

    if (w == 0) {
        float M = -CUDART_INF_F;
#pragma unroll
        for (int i = 0; i < NWARPS; i++) M = fmaxf(M, sm_m[i]);

        float  L = 0.f;
        float4 o = make_float4(0.f, 0.f, 0.f, 0.f);
#pragma unroll
        for (int i = 0; i < NWARPS; i++) {
            if (sm_l[i] == 0.f) continue;   // warp saw no positions
            const float c = __expf(sm_m[i] - M);
            L += c * sm_l[i];
            o.x += c * sm_acc[i][lane * 4 + 0];
            o.y += c * sm_acc[i][lane * 4 + 1];
            o.z += c * sm_acc[i][lane * 4 + 2];
            o.w += c * sm_acc[i][lane * 4 + 3];
        }
        g_pm[bid] = M;
        g_pl[bid] = L;
        reinterpret_cast<float4*>(g_pacc + (size_t)bid * DD)[lane] = o;

        // ---- fused cross-split combine: last CTA per (b,h) merges ----
        __threadfence();
        int done = 0;
        if (lane == 0) done = atomicAdd(&g_cnt[bh], 1);
        done = __shfl_sync(0xffffffffu, done, 0);

        if (done == NSPLITS - 1) {
            float GM = -CUDART_INF_F;
#pragma unroll
            for (int i = 0; i < NSPLITS; i++)
                GM = fmaxf(GM, __ldcg(&g_pm[bh * NSPLITS + i]));

            float  GL = 0.f;
            float4 go = make_float4(0.f, 0.f, 0.f, 0.f);
#pragma unroll
            for (int i = 0; i < NSPLITS; i++) {
                const int idx = bh * NSPLITS + i;
                const float li = __ldcg(&g_pl[idx]);
                if (li == 0.f) continue;
                const float c = __expf(__ldcg(&g_pm[idx]) - GM);
                GL += c * li;
                const float4 a = __ldcg(reinterpret_cast<const float4*>(
                    g_pacc + (size_t)idx * DD) + lane);
                go.x += c * a.x; go.y += c * a.y;
                go.z += c * a.z; go.w += c * a.w;
            }
            const float inv = 1.f / GL;
            const float4 r = make_float4(go.x * inv, go.y * inv,
                                         go.z * inv, go.w * inv);
            reinterpret_cast<float4*>(out + (size_t)bh * DD)[lane] = r;

            if (lane == 0) g_cnt[bh] = 0;   // reset for next graph replay
        }
    }
}

// ---------------------------------------------------------------------------
extern "C" void kernel_launch(void* const* d_in, const int* in_sizes, int n_in,
                              void* d_out, int out_size) {
    // Identify inputs defensively by element count:
    //   x: B*H*D = 16384 fp32, kv: 2*B*S*H*D fp32 (largest), current_pos: 1 int
    const float* x  = nullptr;
    const float* kv = nullptr;
    const int*   cp = nullptr;
    long long best_kv = -1;
    for (int i = 0; i < n_in; i++) {
        if (in_sizes[i] == 1) cp = (const int*)d_in[i];
        else if (in_sizes[i] == BB * HH * DD) x = (const float*)d_in[i];
        else if ((long long)in_sizes[i] > best_kv) {
            best_kv = in_sizes[i];
            kv = (const float*)d_in[i];
        }
    }

    attn_split_kernel<<<NBH * NSPLITS, NWARPS * 32>>>(x, kv, cp, (float*)d_out);
}

// round 6
// speedup vs baseline: 1.6470x; 1.0450x over previous
#include <cuda_runtime.h>
#include <math_constants.h>

// Problem shape (fixed by the dataset)
#define BB 4
#define HH 32
#define DD 128
#define SS 8192
#define NSPLITS 16        // finer work items; grid = 128*16 = 2048 CTAs
#define NWARPS 2          // 64-thread CTAs -> same warps/SM as R2 best config
#define NBH (BB * HH)     // 128
#define SCALE 0.08838834764831845f   // 1/sqrt(128)

// Scratch for split-KV partials (device globals: allocation-free)
__device__ float g_pm[NBH * NSPLITS];
__device__ float g_pl[NBH * NSPLITS];
__device__ float g_pacc[NBH * NSPLITS * DD];
__device__ int   g_cnt[NBH];   // zero-init; self-resetting -> graph-replay safe

__device__ __forceinline__ float warp_sum(float v) {
#pragma unroll
    for (int o = 16; o > 0; o >>= 1)
        v += __shfl_xor_sync(0xffffffffu, v, o);
    return v;
}

__device__ __forceinline__ float dot4(const float4 a, const float4 b) {
    return a.x * b.x + a.y * b.y + a.z * b.z + a.w * b.w;
}

__device__ __forceinline__ float4 ldcs4(const float* p) {
    return __ldcs(reinterpret_cast<const float4*>(p));
}

// ---------------------------------------------------------------------------
// One CTA = one (b, h, split). Warps stride positions inside the split chunk.
// Lane owns dims [4*lane, 4*lane+4). Combine is fused: the last CTA per (b,h)
// merges all split partials and writes the final output.
// Mainloop: 4x position unroll -> 8 streaming float4 loads in flight per warp
// (R2's best-measured configuration).
// ---------------------------------------------------------------------------
__global__ __launch_bounds__(NWARPS * 32)
void attn_split_kernel(const float* __restrict__ x,
                       const float* __restrict__ kv,
                       const int*   __restrict__ cur_pos,
                       float*       __restrict__ out) {
    const int bid   = blockIdx.x;            // b*H*NSPLITS + h*NSPLITS + split
    const int bh    = bid / NSPLITS;
    const int h     = bh % HH;
    const int b     = bh / HH;
    const int split = bid % NSPLITS;

    const int tid  = threadIdx.x;
    const int lane = tid & 31;
    const int w    = tid >> 5;

    const int len   = *cur_pos + 1;                      // valid positions
    const int chunk = (len + NSPLITS - 1) / NSPLITS;
    const int s0    = split * chunk;
    const int s1    = min(len, s0 + chunk);

    // q[b,0,h,:] — lane's 4 dims
    const float4 q = *reinterpret_cast<const float4*>(
        x + (size_t)(b * HH + h) * DD + lane * 4);

    const size_t row_stride = (size_t)HH * DD;           // stride over s
    const size_t kv_half    = (size_t)BB * SS * HH * DD; // K->V offset
    const float* Kp = kv + (size_t)b * SS * row_stride + (size_t)h * DD + lane * 4;
    const float* Vp = Kp + kv_half;

    float  m = -CUDART_INF_F;
    float  l = 0.f;
    float4 acc = make_float4(0.f, 0.f, 0.f, 0.f);

    int s = s0 + w;
    // 4x unroll: 8 streaming float4 loads in flight before dependent math,
    // single max/rescale per group -> 4 independent __expf's.
    for (; s + 3 * NWARPS < s1; s += 4 * NWARPS) {
        const float4 k0 = ldcs4(Kp + (size_t)(s             ) * row_stride);
        const float4 v0 = ldcs4(Vp + (size_t)(s             ) * row_stride);
        const float4 k1 = ldcs4(Kp + (size_t)(s +     NWARPS) * row_stride);
        const float4 v1 = ldcs4(Vp + (size_t)(s +     NWARPS) * row_stride);
        const float4 k2 = ldcs4(Kp + (size_t)(s + 2 * NWARPS) * row_stride);
        const float4 v2 = ldcs4(Vp + (size_t)(s + 2 * NWARPS) * row_stride);
        const float4 k3 = ldcs4(Kp + (size_t)(s + 3 * NWARPS) * row_stride);
        const float4 v3 = ldcs4(Vp + (size_t)(s + 3 * NWARPS) * row_stride);

        const float sc0 = warp_sum(dot4(k0, q)) * SCALE;
        const float sc1 = warp_sum(dot4(k1, q)) * SCALE;
        const float sc2 = warp_sum(dot4(k2, q)) * SCALE;
        const float sc3 = warp_sum(dot4(k3, q)) * SCALE;

        const float mn = fmaxf(fmaxf(fmaxf(m, sc0), fmaxf(sc1, sc2)), sc3);
        const float corr = __expf(m - mn);
        const float p0 = __expf(sc0 - mn);
        const float p1 = __expf(sc1 - mn);
        const float p2 = __expf(sc2 - mn);
        const float p3 = __expf(sc3 - mn);
        m = mn;
        l = l * corr + ((p0 + p1) + (p2 + p3));
        acc.x = acc.x * corr + (p0 * v0.x + p1 * v1.x) + (p2 * v2.x + p3 * v3.x);
        acc.y = acc.y * corr + (p0 * v0.y + p1 * v1.y) + (p2 * v2.y + p3 * v3.y);
        acc.z = acc.z * corr + (p0 * v0.z + p1 * v1.z) + (p2 * v2.z + p3 * v3.z);
        acc.w = acc.w * corr + (p0 * v0.w + p1 * v1.w) + (p2 * v2.w + p3 * v3.w);
    }
    for (; s < s1; s += NWARPS) {
        const float4 kk = ldcs4(Kp + (size_t)s * row_stride);
        const float4 vv = ldcs4(Vp + (size_t)s * row_stride);
        const float sc = warp_sum(dot4(kk, q)) * SCALE;
        const float mn   = fmaxf(m, sc);
        const float corr = __expf(m - mn);
        const float p    = __expf(sc - mn);
        m = mn;
        l = l * corr + p;
        acc.x = acc.x * corr + p * vv.x;
        acc.y = acc.y * corr + p * vv.y;
        acc.z = acc.z * corr + p * vv.z;
        acc.w = acc.w * corr + p * vv.w;
    }

    // ---- combine the NWARPS warps of this CTA ----
    __shared__ float sm_m[NWARPS];
    __shared__ float sm_l[NWARPS];
    __shared__ float sm_acc[NWARPS][DD];

    if (lane == 0) { sm_m[w] = m; sm_l[w] = l; }
    sm_acc[w][lane * 4 + 0] = acc.x;
    sm_acc[w][lane * 4 + 1] = acc.y;
    sm_acc[w][lane * 4 + 2] = acc.z;
    sm_acc[w][lane * 4 + 3] = acc.w;
    __syncthreads();

    if (w == 0) {
        float M = -CUDART_INF_F;
#pragma unroll
        for (int i = 0; i < NWARPS; i++) M = fmaxf(M, sm_m[i]);

        float  L = 0.f;
        float4 o = make_float4(0.f, 0.f, 0.f, 0.f);
#pragma unroll
        for (int i = 0; i < NWARPS; i++) {
            if (sm_l[i] == 0.f) continue;   // warp saw no positions
            const float c = __expf(sm_m[i] - M);
            L += c * sm_l[i];
            o.x += c * sm_acc[i][lane * 4 + 0];
            o.y += c * sm_acc[i][lane * 4 + 1];
            o.z += c * sm_acc[i][lane * 4 + 2];
            o.w += c * sm_acc[i][lane * 4 + 3];
        }
        g_pm[bid] = M;
        g_pl[bid] = L;
        reinterpret_cast<float4*>(g_pacc + (size_t)bid * DD)[lane] = o;

        // ---- fused cross-split combine: last CTA per (b,h) merges ----
        __threadfence();
        int done = 0;
        if (lane == 0) done = atomicAdd(&g_cnt[bh], 1);
        done = __shfl_sync(0xffffffffu, done, 0);

        if (done == NSPLITS - 1) {
            float GM = -CUDART_INF_F;
#pragma unroll
            for (int i = 0; i < NSPLITS; i++)
                GM = fmaxf(GM, __ldcg(&g_pm[bh * NSPLITS + i]));

            float  GL = 0.f;
            float4 go = make_float4(0.f, 0.f, 0.f, 0.f);
#pragma unroll
            for (int i = 0; i < NSPLITS; i++) {
                const int idx = bh * NSPLITS + i;
                const float li = __ldcg(&g_pl[idx]);
                if (li == 0.f) continue;
                const float c = __expf(__ldcg(&g_pm[idx]) - GM);
                GL += c * li;
                const float4 a = __ldcg(reinterpret_cast<const float4*>(
                    g_pacc + (size_t)idx * DD) + lane);
                go.x += c * a.x; go.y += c * a.y;
                go.z += c * a.z; go.w += c * a.w;
            }
            const float inv = 1.f / GL;
            const float4 r = make_float4(go.x * inv, go.y * inv,
                                         go.z * inv, go.w * inv);
            reinterpret_cast<float4*>(out + (size_t)bh * DD)[lane] = r;

            if (lane == 0) g_cnt[bh] = 0;   // reset for next graph replay
        }
    }
}

// ---------------------------------------------------------------------------
extern "C" void kernel_launch(void* const* d_in, const int* in_sizes, int n_in,
                              void* d_out, int out_size) {
    // Identify inputs defensively by element count:
    //   x: B*H*D = 16384 fp32, kv: 2*B*S*H*D fp32 (largest), current_pos: 1 int
    const float* x  = nullptr;
    const float* kv = nullptr;
    const int*   cp = nullptr;
    long long best_kv = -1;
    for (int i = 0; i < n_in; i++) {
        if (in_sizes[i] == 1) cp = (const int*)d_in[i];
        else if (in_sizes[i] == BB * HH * DD) x = (const float*)d_in[i];
        else if ((long long)in_sizes[i] > best_kv) {
            best_kv = in_sizes[i];
            kv = (const float*)d_in[i];
        }
    }

    attn_split_kernel<<<NBH * NSPLITS, NWARPS * 32>>>(x, kv, cp, (float*)d_out);
}